// round 6
// baseline (speedup 1.0000x reference)
#include <cuda_runtime.h>
#include <cstdint>

// Depthwise Conv1d, K=3, pad=1, stride=1.
// inputs: [B=32, C=128, L=8192] f32, weight: [128,3] f32, bias: [128] f32
// out[b,c,l] = w0*x[l-1] + w1*x[l] + w2*x[l+1] + bias  (x zero-padded)
//
// 16 elems/thread (4x float4). Warps are row-aligned: halos by shuffle,
// weights warp-uniform. Streaming cache hints (.cs) on the bulk load/store
// streams: 256 MiB touched exactly once, so L2 retention is pure churn.

#define C_CH   128
#define L_LEN  8192
#define ELEMS_PER_THREAD 16
#define GROUPS_PER_ROW   (L_LEN / ELEMS_PER_THREAD)    // 512
#define TOTAL_ROWS       (32 * C_CH)                   // 4096

__global__ __launch_bounds__(256)
void dwconv1d_kernel(const float* __restrict__ x,
                     const float* __restrict__ w,
                     const float* __restrict__ b,
                     float* __restrict__ y) {
    const int t    = blockIdx.x * blockDim.x + threadIdx.x;  // group index
    const int lane = threadIdx.x & 31;
    const int row  = t >> 9;                // (b*C + c), warp-uniform
    const int pos  = (t & 511) << 4;        // start element within row
    const int c    = row & (C_CH - 1);      // warp-uniform channel

    const float* __restrict__ xr = x + (size_t)row * L_LEN;
    float*       __restrict__ yr = y + (size_t)row * L_LEN;

    // Payload: 4 x LDG.128.cs, front-batched for MLP
    const float4 v0 = __ldcs(reinterpret_cast<const float4*>(xr + pos));
    const float4 v1 = __ldcs(reinterpret_cast<const float4*>(xr + pos + 4));
    const float4 v2 = __ldcs(reinterpret_cast<const float4*>(xr + pos + 8));
    const float4 v3 = __ldcs(reinterpret_cast<const float4*>(xr + pos + 12));

    // Warp-edge halos: only lane 0 / lane 31 touch memory.
    float xl_edge = 0.0f, xh_edge = 0.0f;
    if (lane == 0 && pos != 0)
        xl_edge = __ldca(xr + pos - 1);          // neighbor warp re-reads: keep cached
    if (lane == 31 && pos != L_LEN - ELEMS_PER_THREAD)
        xh_edge = __ldca(xr + pos + 16);

    // Interior halos via shuffle.
    float xl = __shfl_up_sync(0xffffffffu, v3.w, 1);
    float xh = __shfl_down_sync(0xffffffffu, v0.x, 1);
    if (lane == 0)  xl = xl_edge;
    if (lane == 31) xh = xh_edge;

    // Warp-uniform coefficient broadcast (tiny, keep cached)
    const float w0 = __ldg(&w[3 * c + 0]);
    const float w1 = __ldg(&w[3 * c + 1]);
    const float w2 = __ldg(&w[3 * c + 2]);
    const float bb = __ldg(&b[c]);

    float in[18];
    in[0]  = xl;
    in[1]  = v0.x; in[2]  = v0.y; in[3]  = v0.z; in[4]  = v0.w;
    in[5]  = v1.x; in[6]  = v1.y; in[7]  = v1.z; in[8]  = v1.w;
    in[9]  = v2.x; in[10] = v2.y; in[11] = v2.z; in[12] = v2.w;
    in[13] = v3.x; in[14] = v3.y; in[15] = v3.z; in[16] = v3.w;
    in[17] = xh;

    float4 o[4];
    float* op = reinterpret_cast<float*>(o);
#pragma unroll
    for (int i = 0; i < 16; i++) {
        op[i] = fmaf(w0, in[i], fmaf(w1, in[i + 1], fmaf(w2, in[i + 2], bb)));
    }

    // Streaming stores: evict-first, no L2 retention of dead output lines.
    float4* yv = reinterpret_cast<float4*>(yr + pos);
    __stcs(yv + 0, o[0]);
    __stcs(yv + 1, o[1]);
    __stcs(yv + 2, o[2]);
    __stcs(yv + 3, o[3]);
}

extern "C" void kernel_launch(void* const* d_in, const int* in_sizes, int n_in,
                              void* d_out, int out_size) {
    const float* x = (const float*)d_in[0];   // inputs [32,128,8192]
    const float* w = (const float*)d_in[1];   // weight [128,3]
    const float* b = (const float*)d_in[2];   // bias   [128]
    float* y = (float*)d_out;

    const int total_groups = TOTAL_ROWS * GROUPS_PER_ROW;    // 2,097,152
    dwconv1d_kernel<<<total_groups / 256, 256>>>(x, w, b, y);
}